// round 10
// baseline (speedup 1.0000x reference)
#include <cuda_runtime.h>
#include <cuda_bf16.h>
#include <cstdint>

#define BSZ     128
#define DTOT    196608          // 3*256*256
#define KSTAGE  32
#define CHUNK   672             // 21 stages of 32 (last block: 12 stages)
#define NBLK    293             // ceil(196608/672)
#define REGW    0.01f
#define NUM_SINK 10
#define LOG_AB  (-4.852030263919617f)   // log(1/128)

// -------- device scratch (static: no allocations allowed) --------
__device__ float g_part[NBLK][BSZ * BSZ];   // per-block GEMM partials (~19 MB)
__device__ float g_x2p[NBLK][BSZ];
__device__ float g_y2p[NBLK][BSZ];
__device__ float g_C[BSZ * BSZ];

__device__ __forceinline__ unsigned smem_u32(const void* p) {
    return (unsigned)__cvta_generic_to_shared(p);
}

__device__ __forceinline__ void cp16(void* dst, const void* src) {
    asm volatile("cp.async.cg.shared.global [%0], [%1], 16;\n"
                 :: "r"(smem_u32(dst)), "l"(src));
}
#define CP_COMMIT() asm volatile("cp.async.commit_group;\n" ::: "memory")
#define CP_WAIT1()  asm volatile("cp.async.wait_group 1;\n" ::: "memory")

#define MMA_BF16(d, A, bx, by)                                                  \
    asm volatile("mma.sync.aligned.m16n8k16.row.col.f32.bf16.bf16.f32 "         \
                 "{%0,%1,%2,%3}, {%4,%5,%6,%7}, {%8,%9}, {%0,%1,%2,%3};"        \
                 : "+f"(d[0]), "+f"(d[1]), "+f"(d[2]), "+f"(d[3])               \
                 : "r"(A[0]), "r"(A[1]), "r"(A[2]), "r"(A[3]), "r"(bx), "r"(by))

#define LDSM_X4(r, p)                                                           \
    asm volatile("ldmatrix.sync.aligned.m8n8.x4.shared.b16 {%0,%1,%2,%3}, [%4];"\
                 : "=r"(r[0]), "=r"(r[1]), "=r"(r[2]), "=r"(r[3])               \
                 : "r"(smem_u32(p)))

// bf16 tile: 128 rows x 32 k, 64B/row, XOR swizzle on 16B chunks:
//   phys = row*64 + ((chunk ^ ((row>>1)&3))<<4) + within
__device__ __forceinline__ unsigned swz(unsigned row, unsigned bytecol) {
    const unsigned chunk = bytecol >> 4;
    const unsigned rest  = bytecol & 15;
    return row * 64 + (((chunk ^ ((row >> 1) & 3)) << 4)) + rest;
}

// ---- gemm smem layout (bytes) ----
#define RAW_PER_ARR  4096               // floats: 128 rows * 32
#define RAW_PER_STG  (3 * RAW_PER_ARR)  // floats
#define RAW_STG_B    (RAW_PER_STG * 4)  // 49152 bytes
#define AS_OFF       (2 * RAW_STG_B)    // 98304
#define BS_OFF       (AS_OFF + 8192)    // 106496
#define GEMM_SMEM    (BS_OFF + 8192)    // 114688 bytes (112 KB) -> 2 blocks/SM

// =====================================================================
// Kernel A: split-K bf16 GEMM of Delta @ Target^T + fp32 row norms.
// 256 threads (8 warps, 32x64 warp tiles), cp.async depth-2 raw staging,
// swizzled bf16 tiles. 2 blocks resident per SM for phase overlap.
// =====================================================================
__global__ void __launch_bounds__(256, 2)
gemm_kernel(const float* __restrict__ gi,   // imgs
            const float* __restrict__ gw,   // imgs_w
            const float* __restrict__ gt)   // target
{
    extern __shared__ unsigned char smem[];

    const int t       = threadIdx.x;
    const int blk     = blockIdx.x;
    const int k0      = blk * CHUNK;
    const int kcount  = min(CHUNK, DTOT - k0);
    const int nstages = kcount / KSTAGE;     // 21 (last block: 12)

    const int lane = t & 31;
    const int warp = t >> 5;
    const int wm   = (warp >> 1) * 32;    // output row base (4 m-bands)
    const int wn   = (warp & 1) * 64;     // output col base (2 n-bands)

    float acc[2][8][4];
#pragma unroll
    for (int a = 0; a < 2; ++a)
#pragma unroll
        for (int b = 0; b < 8; ++b)
#pragma unroll
            for (int r = 0; r < 4; ++r) acc[a][b][r] = 0.f;

    // convert-phase mapping: thread handles 4 rows (t>>3 + 32q), cseg floats
    const int rbase = t >> 3;             // 0..31
    const int cseg  = (t & 7) * 4;        // float col 0,4,..,28
    // bf16 write target within row: byte = (t&7)*8
    const unsigned wchunk = (unsigned)((t & 7) >> 1);
    const unsigned whalf  = (unsigned)((t & 7) & 1) * 8;

    // cp.async mapping: 1024 16B-chunks per array per stage; 4 per thread
    float x2[4] = {0.f, 0.f, 0.f, 0.f};
    float y2[4] = {0.f, 0.f, 0.f, 0.f};

    // ---- prologue: issue raw stages 0,1 ----
#pragma unroll
    for (int s = 0; s < 2; ++s) {
        if (s < nstages) {
            float* base = (float*)(smem + (s & 1) * RAW_STG_B);
#pragma unroll
            for (int q = 0; q < 4; ++q) {
                const int ch  = t + 256 * q;
                const int row = ch >> 3;
                const int col = (ch & 7) * 4;
                const size_t g = (size_t)row * DTOT + k0 + (size_t)s * KSTAGE + col;
                const int so = row * 32 + col;
                cp16(base + so,                   gi + g);
                cp16(base + RAW_PER_ARR + so,     gw + g);
                cp16(base + 2 * RAW_PER_ARR + so, gt + g);
            }
        }
        CP_COMMIT();
    }

    for (int s = 0; s < nstages; ++s) {
        CP_WAIT1();
        __syncthreads();   // raw stage s visible to all

        const float* ri = (const float*)(smem + (s & 1) * RAW_STG_B);
        const float* rw = ri + RAW_PER_ARR;
        const float* rt = ri + 2 * RAW_PER_ARR;

        // ---- convert: delta -> As, target -> Bs (bf16, swizzled), norms ----
#pragma unroll
        for (int q = 0; q < 4; ++q) {
            const int row = rbase + 32 * q;
            const int o   = row * 32 + cseg;
            float4 i4 = *(const float4*)(ri + o);
            float4 w4 = *(const float4*)(rw + o);
            float4 t4 = *(const float4*)(rt + o);
            float4 d;
            d.x = w4.x - i4.x; d.y = w4.y - i4.y;
            d.z = w4.z - i4.z; d.w = w4.w - i4.w;
            x2[q] += d.x*d.x + d.y*d.y + d.z*d.z + d.w*d.w;
            y2[q] += t4.x*t4.x + t4.y*t4.y + t4.z*t4.z + t4.w*t4.w;

            const unsigned wo = (unsigned)row * 64 +
                                ((wchunk ^ (((unsigned)row >> 1) & 3)) << 4) + whalf;
            __nv_bfloat162 p0 = __float22bfloat162_rn(make_float2(d.x, d.y));
            __nv_bfloat162 p1 = __float22bfloat162_rn(make_float2(d.z, d.w));
            uint2 u; u.x = reinterpret_cast<unsigned&>(p0);
            u.y = reinterpret_cast<unsigned&>(p1);
            *(uint2*)(smem + AS_OFF + wo) = u;
            __nv_bfloat162 q0 = __float22bfloat162_rn(make_float2(t4.x, t4.y));
            __nv_bfloat162 q1 = __float22bfloat162_rn(make_float2(t4.z, t4.w));
            uint2 v; v.x = reinterpret_cast<unsigned&>(q0);
            v.y = reinterpret_cast<unsigned&>(q1);
            *(uint2*)(smem + BS_OFF + wo) = v;
        }

        __syncthreads();   // bf16 tiles visible; raw[s&1] fully consumed

        // refill raw buffer (s&1) with stage s+2
        if (s + 2 < nstages) {
            float* base = (float*)(smem + (s & 1) * RAW_STG_B);
            const size_t adv = (size_t)(s + 2) * KSTAGE;
#pragma unroll
            for (int q = 0; q < 4; ++q) {
                const int ch  = t + 256 * q;
                const int row = ch >> 3;
                const int col = (ch & 7) * 4;
                const size_t g = (size_t)row * DTOT + k0 + adv + col;
                const int so = row * 32 + col;
                cp16(base + so,                   gi + g);
                cp16(base + RAW_PER_ARR + so,     gw + g);
                cp16(base + 2 * RAW_PER_ARR + so, gt + g);
            }
        }
        CP_COMMIT();

        // ---- MMA: warp computes 32x64 on this 32-k tile ----
#pragma unroll
        for (int kk = 0; kk < KSTAGE; kk += 16) {
            const int lr = lane & 15;
            const unsigned bc = (unsigned)(kk + (lane >> 4) * 8) * 2;  // byte col
            unsigned a0[4], a1[4];
            LDSM_X4(a0, smem + AS_OFF + swz((unsigned)(wm + lr),      bc));
            LDSM_X4(a1, smem + AS_OFF + swz((unsigned)(wm + 16 + lr), bc));
            unsigned bb[4][4];
#pragma unroll
            for (int qb = 0; qb < 4; ++qb)
                LDSM_X4(bb[qb], smem + BS_OFF + swz((unsigned)(wn + qb * 16 + lr), bc));
#pragma unroll
            for (int nj = 0; nj < 8; ++nj) {
                const int qb = nj >> 1;
                const int hi = nj & 1;
                MMA_BF16(acc[0][nj], a0, bb[qb][hi], bb[qb][hi + 2]);
                MMA_BF16(acc[1][nj], a1, bb[qb][hi], bb[qb][hi + 2]);
            }
        }
        __syncthreads();   // all ldsm reads done before next convert overwrites
    }

    // ---- write per-block GEMM partials ----
    float* op = g_part[blk];
    const int g  = lane >> 2;
    const int tt = lane & 3;
#pragma unroll
    for (int mi = 0; mi < 2; ++mi)
#pragma unroll
        for (int nj = 0; nj < 8; ++nj) {
            const int r  = wm + mi * 16 + g;
            const int cc = wn + nj * 8 + tt * 2;
            *(float2*)&op[r * 128 + cc]       = make_float2(acc[mi][nj][0], acc[mi][nj][1]);
            *(float2*)&op[(r + 8) * 128 + cc] = make_float2(acc[mi][nj][2], acc[mi][nj][3]);
        }

    // ---- norms: reduce over the 8 threads sharing each row, write 4 rows ----
#pragma unroll
    for (int q = 0; q < 4; ++q) {
#pragma unroll
        for (int d = 4; d; d >>= 1) {
            x2[q] += __shfl_down_sync(0xffffffffu, x2[q], d, 8);
            y2[q] += __shfl_down_sync(0xffffffffu, y2[q], d, 8);
        }
    }
    if ((t & 7) == 0) {
#pragma unroll
        for (int q = 0; q < 4; ++q) {
            g_x2p[blk][rbase + 32 * q] = x2[q];
            g_y2p[blk][rbase + 32 * q] = y2[q];
        }
    }
}

// =====================================================================
// Kernel B: reduce split-K partials, assemble C = sqrt(max(x2+y2-2xy,0))
// =====================================================================
__global__ void reduce_kernel()
{
    const int i = blockIdx.x;
    const int j = threadIdx.x;
    float xy = 0.f, x2 = 0.f, y2 = 0.f;
#pragma unroll 7
    for (int b = 0; b < NBLK; ++b) {
        xy += g_part[b][i * 128 + j];
        x2 += g_x2p[b][i];
        y2 += g_y2p[b][j];
    }
    const float sq = fmaxf(x2 + y2 - 2.f * xy, 0.f);
    g_C[i * 128 + j] = sqrtf(sq);
}

// =====================================================================
// Kernel C: single-block Sinkhorn, 128 threads (row-per-thread matvecs).
//   K = exp(C - m); per iteration:
//     S_i = K[i,:].beta ; u_i = REG*(log_a + u_i - m - log S_i); alpha=exp(-u)
//     T_j = K[:,j].alpha; v_j = REG*(log_b + v_j - m - log T_j); beta =exp(-v)
//   out = (sum u + sum v)/128.  Contraction ~2*REG/iter -> 10 iters suffice.
// =====================================================================
__global__ void __launch_bounds__(128, 1)
sinkhorn_kernel(float* __restrict__ out)
{
    extern __shared__ float sm[];
    float* Krow = sm;                     // 128*132
    float* Kcol = Krow + 128 * 132;       // 128*132 (transposed copy)
    float* uu   = Kcol + 128 * 132;       // 128
    float* vv   = uu + 128;
    float* alp  = vv + 128;
    float* bet  = alp + 128;
    float* red  = bet + 128;              // 8

    const int tid  = threadIdx.x;
    const int lane = tid & 31;
    const int w    = tid >> 5;

    const float4* Crow4 = (const float4*)(g_C + tid * 128);

    // pass 1: global max of C
    float lm = -3.4e38f;
#pragma unroll
    for (int q = 0; q < 32; ++q) {
        const float4 c = Crow4[q];
        lm = fmaxf(lm, fmaxf(fmaxf(c.x, c.y), fmaxf(c.z, c.w)));
    }
#pragma unroll
    for (int d = 16; d; d >>= 1) lm = fmaxf(lm, __shfl_xor_sync(0xffffffffu, lm, d));
    if (lane == 0) red[w] = lm;
    __syncthreads();
    if (tid == 0) red[4] = fmaxf(fmaxf(red[0], red[1]), fmaxf(red[2], red[3]));
    __syncthreads();
    const float m = red[4];

    // pass 2: build K row-major + transposed copy
#pragma unroll
    for (int q = 0; q < 32; ++q) {
        const float4 c = Crow4[q];
        const float k0 = __expf(c.x - m);
        const float k1 = __expf(c.y - m);
        const float k2 = __expf(c.z - m);
        const float k3 = __expf(c.w - m);
        *(float4*)&Krow[tid * 132 + q * 4] = make_float4(k0, k1, k2, k3);
        Kcol[(q * 4 + 0) * 132 + tid] = k0;
        Kcol[(q * 4 + 1) * 132 + tid] = k1;
        Kcol[(q * 4 + 2) * 132 + tid] = k2;
        Kcol[(q * 4 + 3) * 132 + tid] = k3;
    }
    uu[tid] = 0.f; vv[tid] = 0.f; bet[tid] = 1.f;
    __syncthreads();

    const float4* Kr4 = (const float4*)(Krow + tid * 132);
    const float4* Kc4 = (const float4*)(Kcol + tid * 132);
    const float4* b4  = (const float4*)bet;
    const float4* a4  = (const float4*)alp;

    for (int it = 0; it < NUM_SINK; ++it) {
        // ---- u phase ----
        float s = 0.f;
#pragma unroll
        for (int q = 0; q < 32; ++q) {
            const float4 k = Kr4[q];
            const float4 b = b4[q];
            s = fmaf(k.x, b.x, s); s = fmaf(k.y, b.y, s);
            s = fmaf(k.z, b.z, s); s = fmaf(k.w, b.w, s);
        }
        const float un = REGW * (LOG_AB + uu[tid] - m - __logf(s));
        uu[tid]  = un;
        alp[tid] = __expf(-un);
        __syncthreads();

        // ---- v phase ----
        float ts = 0.f;
#pragma unroll
        for (int q = 0; q < 32; ++q) {
            const float4 k = Kc4[q];
            const float4 a = a4[q];
            ts = fmaf(k.x, a.x, ts); ts = fmaf(k.y, a.y, ts);
            ts = fmaf(k.z, a.z, ts); ts = fmaf(k.w, a.w, ts);
        }
        const float vn = REGW * (LOG_AB + vv[tid] - m - __logf(ts));
        vv[tid]  = vn;
        bet[tid] = __expf(-vn);
        __syncthreads();
    }

    // out = (sum u + sum v) / 128
    float val = uu[tid] + vv[tid];
#pragma unroll
    for (int d = 16; d; d >>= 1) val += __shfl_xor_sync(0xffffffffu, val, d);
    if (lane == 0) red[w] = val;
    __syncthreads();
    if (tid == 0)
        out[0] = (red[0] + red[1] + red[2] + red[3]) * (1.0f / 128.0f);
}

// =====================================================================
extern "C" void kernel_launch(void* const* d_in, const int* in_sizes, int n_in,
                              void* d_out, int out_size)
{
    const float* gi = (const float*)d_in[0];   // imgs
    const float* gw = (const float*)d_in[1];   // imgs_w
    const float* gt = (const float*)d_in[2];   // target
    float* out = (float*)d_out;

    cudaFuncSetAttribute(gemm_kernel,
                         cudaFuncAttributeMaxDynamicSharedMemorySize, GEMM_SMEM);
    const int smem_sink = (2 * 128 * 132 + 4 * 128 + 8) * (int)sizeof(float);
    cudaFuncSetAttribute(sinkhorn_kernel,
                         cudaFuncAttributeMaxDynamicSharedMemorySize, smem_sink);

    gemm_kernel<<<NBLK, 256, GEMM_SMEM>>>(gi, gw, gt);
    reduce_kernel<<<BSZ, BSZ>>>();
    sinkhorn_kernel<<<1, 128, smem_sink>>>(out);
}

// round 11
// speedup vs baseline: 1.3192x; 1.3192x over previous
#include <cuda_runtime.h>
#include <cuda_bf16.h>
#include <cstdint>

#define BSZ     128
#define DTOT    196608          // 3*256*256
#define KSTAGE  32
#define CHUNK   672             // 21 stages of 32 (last block: 12 stages)
#define NBLK    293             // ceil(196608/672)
#define REGW    0.01f
#define NUM_SINK 10
#define LOG_AB  (-4.852030263919617f)   // log(1/128)

// -------- device scratch (static: no allocations allowed) --------
__device__ float g_part[NBLK][BSZ * BSZ];   // per-block GEMM partials (~19 MB)
__device__ float g_x2p[NBLK][BSZ];
__device__ float g_y2p[NBLK][BSZ];
__device__ float g_C[BSZ * BSZ];

__device__ __forceinline__ unsigned smem_u32(const void* p) {
    return (unsigned)__cvta_generic_to_shared(p);
}

__device__ __forceinline__ void cp16(void* dst, const void* src) {
    asm volatile("cp.async.cg.shared.global [%0], [%1], 16;\n"
                 :: "r"(smem_u32(dst)), "l"(src));
}
#define CP_COMMIT() asm volatile("cp.async.commit_group;\n" ::: "memory")
#define CP_WAIT1()  asm volatile("cp.async.wait_group 1;\n" ::: "memory")

#define MMA_BF16(d, A, bx, by)                                                  \
    asm volatile("mma.sync.aligned.m16n8k16.row.col.f32.bf16.bf16.f32 "         \
                 "{%0,%1,%2,%3}, {%4,%5,%6,%7}, {%8,%9}, {%0,%1,%2,%3};"        \
                 : "+f"(d[0]), "+f"(d[1]), "+f"(d[2]), "+f"(d[3])               \
                 : "r"(A[0]), "r"(A[1]), "r"(A[2]), "r"(A[3]), "r"(bx), "r"(by))

#define LDSM_X4(r, p)                                                           \
    asm volatile("ldmatrix.sync.aligned.m8n8.x4.shared.b16 {%0,%1,%2,%3}, [%4];"\
                 : "=r"(r[0]), "=r"(r[1]), "=r"(r[2]), "=r"(r[3])               \
                 : "r"(smem_u32(p)))

// bf16 tile: 128 rows x 32 k, 64B/row, XOR swizzle on 16B chunks
__device__ __forceinline__ unsigned swz(unsigned row, unsigned bytecol) {
    const unsigned chunk = bytecol >> 4;
    const unsigned rest  = bytecol & 15;
    return row * 64 + (((chunk ^ ((row >> 1) & 3)) << 4)) + rest;
}

// ---- gemm smem layout (bytes) ----
#define RAW_PER_ARR  4096               // floats: 128 rows * 32
#define RAW_PER_STG  (3 * RAW_PER_ARR)  // floats
#define RAW_STG_B    (RAW_PER_STG * 4)  // 49152 bytes
#define AS_OFF       (2 * RAW_STG_B)    // 98304
#define BS_OFF       (AS_OFF + 8192)    // 106496
#define GEMM_SMEM    (BS_OFF + 8192)    // 114688 bytes (112 KB) -> 2 blocks/SM

// =====================================================================
// Kernel A: split-K bf16 GEMM of Delta @ Target^T + fp32 row norms.
// 256 threads (8 warps, 32x64 warp tiles), cp.async depth-2 raw staging,
// swizzled bf16 tiles. 2 blocks resident per SM for phase overlap.
// =====================================================================
__global__ void __launch_bounds__(256, 2)
gemm_kernel(const float* __restrict__ gi,   // imgs
            const float* __restrict__ gw,   // imgs_w
            const float* __restrict__ gt)   // target
{
    extern __shared__ unsigned char smem[];

    const int t       = threadIdx.x;
    const int blk     = blockIdx.x;
    const int k0      = blk * CHUNK;
    const int kcount  = min(CHUNK, DTOT - k0);
    const int nstages = kcount / KSTAGE;     // 21 (last block: 12)

    const int lane = t & 31;
    const int warp = t >> 5;
    const int wm   = (warp >> 1) * 32;    // output row base (4 m-bands)
    const int wn   = (warp & 1) * 64;     // output col base (2 n-bands)

    float acc[2][8][4];
#pragma unroll
    for (int a = 0; a < 2; ++a)
#pragma unroll
        for (int b = 0; b < 8; ++b)
#pragma unroll
            for (int r = 0; r < 4; ++r) acc[a][b][r] = 0.f;

    const int rbase = t >> 3;             // 0..31
    const int cseg  = (t & 7) * 4;        // float col 0,4,..,28
    const unsigned wchunk = (unsigned)((t & 7) >> 1);
    const unsigned whalf  = (unsigned)((t & 7) & 1) * 8;

    float x2[4] = {0.f, 0.f, 0.f, 0.f};
    float y2[4] = {0.f, 0.f, 0.f, 0.f};

    // ---- prologue: issue raw stages 0,1 ----
#pragma unroll
    for (int s = 0; s < 2; ++s) {
        if (s < nstages) {
            float* base = (float*)(smem + (s & 1) * RAW_STG_B);
#pragma unroll
            for (int q = 0; q < 4; ++q) {
                const int ch  = t + 256 * q;
                const int row = ch >> 3;
                const int col = (ch & 7) * 4;
                const size_t g = (size_t)row * DTOT + k0 + (size_t)s * KSTAGE + col;
                const int so = row * 32 + col;
                cp16(base + so,                   gi + g);
                cp16(base + RAW_PER_ARR + so,     gw + g);
                cp16(base + 2 * RAW_PER_ARR + so, gt + g);
            }
        }
        CP_COMMIT();
    }

    for (int s = 0; s < nstages; ++s) {
        CP_WAIT1();
        __syncthreads();   // raw stage s visible to all

        const float* ri = (const float*)(smem + (s & 1) * RAW_STG_B);
        const float* rw = ri + RAW_PER_ARR;
        const float* rt = ri + 2 * RAW_PER_ARR;

        // ---- convert: delta -> As, target -> Bs (bf16, swizzled), norms ----
#pragma unroll
        for (int q = 0; q < 4; ++q) {
            const int row = rbase + 32 * q;
            const int o   = row * 32 + cseg;
            float4 i4 = *(const float4*)(ri + o);
            float4 w4 = *(const float4*)(rw + o);
            float4 t4 = *(const float4*)(rt + o);
            float4 d;
            d.x = w4.x - i4.x; d.y = w4.y - i4.y;
            d.z = w4.z - i4.z; d.w = w4.w - i4.w;
            x2[q] += d.x*d.x + d.y*d.y + d.z*d.z + d.w*d.w;
            y2[q] += t4.x*t4.x + t4.y*t4.y + t4.z*t4.z + t4.w*t4.w;

            const unsigned wo = (unsigned)row * 64 +
                                ((wchunk ^ (((unsigned)row >> 1) & 3)) << 4) + whalf;
            __nv_bfloat162 p0 = __float22bfloat162_rn(make_float2(d.x, d.y));
            __nv_bfloat162 p1 = __float22bfloat162_rn(make_float2(d.z, d.w));
            uint2 u; u.x = reinterpret_cast<unsigned&>(p0);
            u.y = reinterpret_cast<unsigned&>(p1);
            *(uint2*)(smem + AS_OFF + wo) = u;
            __nv_bfloat162 q0 = __float22bfloat162_rn(make_float2(t4.x, t4.y));
            __nv_bfloat162 q1 = __float22bfloat162_rn(make_float2(t4.z, t4.w));
            uint2 v; v.x = reinterpret_cast<unsigned&>(q0);
            v.y = reinterpret_cast<unsigned&>(q1);
            *(uint2*)(smem + BS_OFF + wo) = v;
        }

        __syncthreads();   // bf16 tiles visible; raw[s&1] fully consumed

        // refill raw buffer (s&1) with stage s+2
        if (s + 2 < nstages) {
            float* base = (float*)(smem + (s & 1) * RAW_STG_B);
            const size_t adv = (size_t)(s + 2) * KSTAGE;
#pragma unroll
            for (int q = 0; q < 4; ++q) {
                const int ch  = t + 256 * q;
                const int row = ch >> 3;
                const int col = (ch & 7) * 4;
                const size_t g = (size_t)row * DTOT + k0 + adv + col;
                const int so = row * 32 + col;
                cp16(base + so,                   gi + g);
                cp16(base + RAW_PER_ARR + so,     gw + g);
                cp16(base + 2 * RAW_PER_ARR + so, gt + g);
            }
        }
        CP_COMMIT();

        // ---- MMA: warp computes 32x64 on this 32-k tile ----
#pragma unroll
        for (int kk = 0; kk < KSTAGE; kk += 16) {
            const int lr = lane & 15;
            const unsigned bc = (unsigned)(kk + (lane >> 4) * 8) * 2;  // byte col
            unsigned a0[4], a1[4];
            LDSM_X4(a0, smem + AS_OFF + swz((unsigned)(wm + lr),      bc));
            LDSM_X4(a1, smem + AS_OFF + swz((unsigned)(wm + 16 + lr), bc));
            unsigned bb[4][4];
#pragma unroll
            for (int qb = 0; qb < 4; ++qb)
                LDSM_X4(bb[qb], smem + BS_OFF + swz((unsigned)(wn + qb * 16 + lr), bc));
#pragma unroll
            for (int nj = 0; nj < 8; ++nj) {
                const int qb = nj >> 1;
                const int hi = nj & 1;
                MMA_BF16(acc[0][nj], a0, bb[qb][hi], bb[qb][hi + 2]);
                MMA_BF16(acc[1][nj], a1, bb[qb][hi], bb[qb][hi + 2]);
            }
        }
        __syncthreads();   // all ldsm reads done before next convert overwrites
    }

    // ---- write per-block GEMM partials ----
    float* op = g_part[blk];
    const int g  = lane >> 2;
    const int tt = lane & 3;
#pragma unroll
    for (int mi = 0; mi < 2; ++mi)
#pragma unroll
        for (int nj = 0; nj < 8; ++nj) {
            const int r  = wm + mi * 16 + g;
            const int cc = wn + nj * 8 + tt * 2;
            *(float2*)&op[r * 128 + cc]       = make_float2(acc[mi][nj][0], acc[mi][nj][1]);
            *(float2*)&op[(r + 8) * 128 + cc] = make_float2(acc[mi][nj][2], acc[mi][nj][3]);
        }

    // ---- norms: reduce over the 8 threads sharing each row, write 4 rows ----
#pragma unroll
    for (int q = 0; q < 4; ++q) {
#pragma unroll
        for (int d = 4; d; d >>= 1) {
            x2[q] += __shfl_down_sync(0xffffffffu, x2[q], d, 8);
            y2[q] += __shfl_down_sync(0xffffffffu, y2[q], d, 8);
        }
    }
    if ((t & 7) == 0) {
#pragma unroll
        for (int q = 0; q < 4; ++q) {
            g_x2p[blk][rbase + 32 * q] = x2[q];
            g_y2p[blk][rbase + 32 * q] = y2[q];
        }
    }
}

// =====================================================================
// Kernel B: parallel reduce of split-K partials.
// 128 blocks x 1024 threads: block i owns row i; the b-dimension is
// split over 8 slices (tid>>7). Fixed-order smem combine -> deterministic.
// =====================================================================
__global__ void __launch_bounds__(1024, 1)
reduce_kernel()
{
    __shared__ float sxy[8][128];
    __shared__ float sy2[8][128];
    __shared__ float sx2[8];

    const int i  = blockIdx.x;
    const int j  = threadIdx.x & 127;
    const int sl = threadIdx.x >> 7;      // 0..7

    float xy = 0.f, y2 = 0.f, x2 = 0.f;
#pragma unroll 4
    for (int b = sl; b < NBLK; b += 8) {
        xy += g_part[b][i * 128 + j];
        y2 += g_y2p[b][j];
        x2 += g_x2p[b][i];                // broadcast load (L2-hot)
    }
    sxy[sl][j] = xy;
    sy2[sl][j] = y2;
    if (j == 0) sx2[sl] = x2;
    __syncthreads();

    if (threadIdx.x < 128) {
        float XY = 0.f, Y2 = 0.f, X2 = 0.f;
#pragma unroll
        for (int s = 0; s < 8; ++s) {
            XY += sxy[s][j];
            Y2 += sy2[s][j];
            X2 += sx2[s];
        }
        const float sq = fmaxf(X2 + Y2 - 2.f * XY, 0.f);
        g_C[i * 128 + j] = sqrtf(sq);
    }
}

// =====================================================================
// Kernel C: single-block Sinkhorn, 128 threads (row-per-thread matvecs).
//   K = exp(C - m); per iteration:
//     S_i = K[i,:].beta ; u_i = REG*(log_a + u_i - m - log S_i); alpha=exp(-u)
//     T_j = K[:,j].alpha; v_j = REG*(log_b + v_j - m - log T_j); beta =exp(-v)
//   out = (sum u + sum v)/128.  Contraction ~2*REG/iter -> 10 iters suffice.
// =====================================================================
__global__ void __launch_bounds__(128, 1)
sinkhorn_kernel(float* __restrict__ out)
{
    extern __shared__ float sm[];
    float* Krow = sm;                     // 128*132
    float* Kcol = Krow + 128 * 132;       // 128*132 (transposed copy)
    float* uu   = Kcol + 128 * 132;       // 128
    float* vv   = uu + 128;
    float* alp  = vv + 128;
    float* bet  = alp + 128;
    float* red  = bet + 128;              // 8

    const int tid  = threadIdx.x;
    const int lane = tid & 31;
    const int w    = tid >> 5;

    const float4* Crow4 = (const float4*)(g_C + tid * 128);

    // pass 1: global max of C
    float lm = -3.4e38f;
#pragma unroll
    for (int q = 0; q < 32; ++q) {
        const float4 c = Crow4[q];
        lm = fmaxf(lm, fmaxf(fmaxf(c.x, c.y), fmaxf(c.z, c.w)));
    }
#pragma unroll
    for (int d = 16; d; d >>= 1) lm = fmaxf(lm, __shfl_xor_sync(0xffffffffu, lm, d));
    if (lane == 0) red[w] = lm;
    __syncthreads();
    if (tid == 0) red[4] = fmaxf(fmaxf(red[0], red[1]), fmaxf(red[2], red[3]));
    __syncthreads();
    const float m = red[4];

    // pass 2: build K row-major + transposed copy
#pragma unroll
    for (int q = 0; q < 32; ++q) {
        const float4 c = Crow4[q];
        const float k0 = __expf(c.x - m);
        const float k1 = __expf(c.y - m);
        const float k2 = __expf(c.z - m);
        const float k3 = __expf(c.w - m);
        *(float4*)&Krow[tid * 132 + q * 4] = make_float4(k0, k1, k2, k3);
        Kcol[(q * 4 + 0) * 132 + tid] = k0;
        Kcol[(q * 4 + 1) * 132 + tid] = k1;
        Kcol[(q * 4 + 2) * 132 + tid] = k2;
        Kcol[(q * 4 + 3) * 132 + tid] = k3;
    }
    uu[tid] = 0.f; vv[tid] = 0.f; bet[tid] = 1.f;
    __syncthreads();

    const float4* Kr4 = (const float4*)(Krow + tid * 132);
    const float4* Kc4 = (const float4*)(Kcol + tid * 132);
    const float4* b4  = (const float4*)bet;
    const float4* a4  = (const float4*)alp;

    for (int it = 0; it < NUM_SINK; ++it) {
        // ---- u phase ----
        float s = 0.f;
#pragma unroll
        for (int q = 0; q < 32; ++q) {
            const float4 k = Kr4[q];
            const float4 b = b4[q];
            s = fmaf(k.x, b.x, s); s = fmaf(k.y, b.y, s);
            s = fmaf(k.z, b.z, s); s = fmaf(k.w, b.w, s);
        }
        const float un = REGW * (LOG_AB + uu[tid] - m - __logf(s));
        uu[tid]  = un;
        alp[tid] = __expf(-un);
        __syncthreads();

        // ---- v phase ----
        float ts = 0.f;
#pragma unroll
        for (int q = 0; q < 32; ++q) {
            const float4 k = Kc4[q];
            const float4 a = a4[q];
            ts = fmaf(k.x, a.x, ts); ts = fmaf(k.y, a.y, ts);
            ts = fmaf(k.z, a.z, ts); ts = fmaf(k.w, a.w, ts);
        }
        const float vn = REGW * (LOG_AB + vv[tid] - m - __logf(ts));
        vv[tid]  = vn;
        bet[tid] = __expf(-vn);
        __syncthreads();
    }

    // out = (sum u + sum v) / 128
    float val = uu[tid] + vv[tid];
#pragma unroll
    for (int d = 16; d; d >>= 1) val += __shfl_xor_sync(0xffffffffu, val, d);
    if (lane == 0) red[w] = val;
    __syncthreads();
    if (tid == 0)
        out[0] = (red[0] + red[1] + red[2] + red[3]) * (1.0f / 128.0f);
}

// =====================================================================
extern "C" void kernel_launch(void* const* d_in, const int* in_sizes, int n_in,
                              void* d_out, int out_size)
{
    const float* gi = (const float*)d_in[0];   // imgs
    const float* gw = (const float*)d_in[1];   // imgs_w
    const float* gt = (const float*)d_in[2];   // target
    float* out = (float*)d_out;

    cudaFuncSetAttribute(gemm_kernel,
                         cudaFuncAttributeMaxDynamicSharedMemorySize, GEMM_SMEM);
    const int smem_sink = (2 * 128 * 132 + 4 * 128 + 8) * (int)sizeof(float);
    cudaFuncSetAttribute(sinkhorn_kernel,
                         cudaFuncAttributeMaxDynamicSharedMemorySize, smem_sink);

    gemm_kernel<<<NBLK, 256, GEMM_SMEM>>>(gi, gw, gt);
    reduce_kernel<<<BSZ, 1024>>>();
    sinkhorn_kernel<<<1, 128, smem_sink>>>(out);
}